// round 2
// baseline (speedup 1.0000x reference)
#include <cuda_runtime.h>
#include <math.h>

#define D_MODEL 768
#define HEADS   12
#define DH      64
#define SEQ     1024
#define BATCH   8
#define ROWS    (BATCH*SEQ)        /* 8192 */
#define ELEMS   (ROWS*D_MODEL)     /* 6291456 */

// Scratch: m1,m2,q1,k1,v1,q2,k2,v2,a1,a2  (10 * 25.2 MB)
__device__ float g_scratch[10ull * ELEMS];

// ---------------------------------------------------------------------------
// LayerNorm: one block per row (768 elems), 256 threads, 3 elems/thread
// ---------------------------------------------------------------------------
__global__ __launch_bounds__(256)
void ln_kernel(const float* __restrict__ x, const float* __restrict__ g,
               const float* __restrict__ b, float* __restrict__ out)
{
    __shared__ float red[16];
    int row = blockIdx.x;
    int tid = threadIdx.x;
    const float* xp = x + (size_t)row * D_MODEL;
    float v0 = xp[tid], v1 = xp[tid + 256], v2 = xp[tid + 512];
    float s  = v0 + v1 + v2;
    float sq = v0*v0 + v1*v1 + v2*v2;
    #pragma unroll
    for (int o = 16; o > 0; o >>= 1) {
        s  += __shfl_down_sync(0xffffffffu, s,  o);
        sq += __shfl_down_sync(0xffffffffu, sq, o);
    }
    int w = tid >> 5, l = tid & 31;
    if (l == 0) { red[w] = s; red[w + 8] = sq; }
    __syncthreads();
    if (tid < 32) {
        float ss = (tid < 8) ? red[tid]     : 0.f;
        float qq = (tid < 8) ? red[tid + 8] : 0.f;
        #pragma unroll
        for (int o = 4; o > 0; o >>= 1) {
            ss += __shfl_down_sync(0xffffffffu, ss, o);
            qq += __shfl_down_sync(0xffffffffu, qq, o);
        }
        if (tid == 0) { red[0] = ss; red[1] = qq; }
    }
    __syncthreads();
    float mu   = red[0] * (1.0f / D_MODEL);
    float var  = red[1] * (1.0f / D_MODEL) - mu * mu;
    float rstd = rsqrtf(var + 1e-5f);
    float* op = out + (size_t)row * D_MODEL;
    op[tid]       = (v0 - mu) * rstd * g[tid]       + b[tid];
    op[tid + 256] = (v1 - mu) * rstd * g[tid + 256] + b[tid + 256];
    op[tid + 512] = (v2 - mu) * rstd * g[tid + 512] + b[tid + 512];
}

// ---------------------------------------------------------------------------
// SGEMM: C[8192,768] = A[8192,768] @ W[768,768] + bias
// 128x128x16 block tile, 256 threads, 8x8 per-thread microtile.
// mode 0: C row-major [row, col]
// mode 1: head layout  q[((b*H + col/64)*SEQ + n)*64 + col%64]
// ---------------------------------------------------------------------------
__global__ __launch_bounds__(256)
void sgemm_kernel(const float* __restrict__ A, const float* __restrict__ W,
                  const float* __restrict__ bias, float* __restrict__ C, int mode)
{
    __shared__ float As[16][128];   // transposed A tile: As[k][m]
    __shared__ float Bs[16][128];   // Bs[k][n]
    int tid = threadIdx.x;
    int bm = blockIdx.y * 128;
    int bn = blockIdx.x * 128;

    int arow = tid >> 2;            // 0..63
    int acol = (tid & 3) << 2;      // 0,4,8,12
    int brow = tid >> 5;            // 0..7
    int bcol = (tid & 31) << 2;     // 0..124
    int tr = (tid >> 4) << 3;       // 0..120
    int tc = (tid & 15) << 3;       // 0..120

    float acc[8][8] = {};

    for (int k0 = 0; k0 < D_MODEL; k0 += 16) {
        #pragma unroll
        for (int rr = 0; rr < 2; rr++) {
            int r = arow + rr * 64;
            float4 a4 = *(const float4*)&A[(size_t)(bm + r) * D_MODEL + k0 + acol];
            As[acol + 0][r] = a4.x;
            As[acol + 1][r] = a4.y;
            As[acol + 2][r] = a4.z;
            As[acol + 3][r] = a4.w;
        }
        #pragma unroll
        for (int rr = 0; rr < 2; rr++) {
            int r = brow + rr * 8;
            *(float4*)&Bs[r][bcol] =
                *(const float4*)&W[(size_t)(k0 + r) * D_MODEL + bn + bcol];
        }
        __syncthreads();
        #pragma unroll
        for (int kk = 0; kk < 16; kk++) {
            float ra[8], rb[8];
            *(float4*)&ra[0] = *(float4*)&As[kk][tr];
            *(float4*)&ra[4] = *(float4*)&As[kk][tr + 4];
            *(float4*)&rb[0] = *(float4*)&Bs[kk][tc];
            *(float4*)&rb[4] = *(float4*)&Bs[kk][tc + 4];
            #pragma unroll
            for (int i = 0; i < 8; i++)
                #pragma unroll
                for (int j = 0; j < 8; j++)
                    acc[i][j] = fmaf(ra[i], rb[j], acc[i][j]);
        }
        __syncthreads();
    }

    #pragma unroll
    for (int i = 0; i < 8; i++) {
        int row = bm + tr + i;
        int bb = row >> 10;         // batch
        int n  = row & (SEQ - 1);   // seq pos
        #pragma unroll
        for (int jj = 0; jj < 8; jj += 4) {
            int col = bn + tc + jj;
            float4 r4;
            r4.x = acc[i][jj + 0] + bias[col + 0];
            r4.y = acc[i][jj + 1] + bias[col + 1];
            r4.z = acc[i][jj + 2] + bias[col + 2];
            r4.w = acc[i][jj + 3] + bias[col + 3];
            if (mode == 0) {
                *(float4*)&C[(size_t)row * D_MODEL + col] = r4;
            } else {
                int h  = col >> 6;
                int dh = col & 63;
                *(float4*)&C[(((size_t)(bb * HEADS + h)) * SEQ + n) * DH + dh] = r4;
            }
        }
    }
}

// ---------------------------------------------------------------------------
// Flash attention (fp32): Q,K,V in [B*H, SEQ, 64]; output written in
// [b, n, h*64+dh] (row-major [8192, 768]) so the out-proj GEMM reads it.
// One block = 64 query rows of one (b,h). 256 threads, 4x4 microtiles.
// ---------------------------------------------------------------------------
#define AT_PAD 68
#define ATTN_SMEM ((4 * 64 * AT_PAD + 3 * 64) * (int)sizeof(float))

__global__ __launch_bounds__(256)
void attn_kernel(const float* __restrict__ Q, const float* __restrict__ K,
                 const float* __restrict__ V, float* __restrict__ O)
{
    extern __shared__ float sm[];
    float* Qt   = sm;                    // [64][AT_PAD], d-major: Qt[d][r]
    float* Kt   = Qt + 64 * AT_PAD;      // [64][AT_PAD], d-major: Kt[d][c]
    float* Vs   = Kt + 64 * AT_PAD;      // [64][AT_PAD], row-major: Vs[k][c]
    float* Ss   = Vs + 64 * AT_PAD;      // [64][AT_PAD], Ss[r][c]
    float* mrow = Ss + 64 * AT_PAD;
    float* lrow = mrow + 64;
    float* arow = lrow + 64;

    int tid = threadIdx.x;
    int bh  = blockIdx.y;
    int q0  = blockIdx.x * 64;
    const float* Qp = Q + (size_t)bh * SEQ * DH;
    const float* Kp = K + (size_t)bh * SEQ * DH;
    const float* Vp = V + (size_t)bh * SEQ * DH;

    int lr = tid >> 4;           // 0..15
    int lc = (tid & 15) << 2;    // 0..60
    #pragma unroll
    for (int r = lr; r < 64; r += 16) {
        float4 q4 = *(const float4*)&Qp[(size_t)(q0 + r) * DH + lc];
        Qt[(lc + 0) * AT_PAD + r] = q4.x;
        Qt[(lc + 1) * AT_PAD + r] = q4.y;
        Qt[(lc + 2) * AT_PAD + r] = q4.z;
        Qt[(lc + 3) * AT_PAD + r] = q4.w;
    }
    if (tid < 64) { mrow[tid] = -INFINITY; lrow[tid] = 0.f; }

    int ty = tid >> 4, tx = tid & 15;
    float acc[4][4] = {};
    __syncthreads();

    for (int kv0 = 0; kv0 < SEQ; kv0 += 64) {
        #pragma unroll
        for (int r = lr; r < 64; r += 16) {
            float4 k4 = *(const float4*)&Kp[(size_t)(kv0 + r) * DH + lc];
            Kt[(lc + 0) * AT_PAD + r] = k4.x;
            Kt[(lc + 1) * AT_PAD + r] = k4.y;
            Kt[(lc + 2) * AT_PAD + r] = k4.z;
            Kt[(lc + 3) * AT_PAD + r] = k4.w;
            float4 v4 = *(const float4*)&Vp[(size_t)(kv0 + r) * DH + lc];
            *(float4*)&Vs[r * AT_PAD + lc] = v4;
        }
        __syncthreads();

        // S = Q @ K^T  (64x64)
        float s[4][4] = {};
        #pragma unroll
        for (int d = 0; d < 64; d++) {
            float4 q4 = *(float4*)&Qt[d * AT_PAD + ty * 4];
            float4 k4 = *(float4*)&Kt[d * AT_PAD + tx * 4];
            float qa[4] = {q4.x, q4.y, q4.z, q4.w};
            float ka[4] = {k4.x, k4.y, k4.z, k4.w};
            #pragma unroll
            for (int i = 0; i < 4; i++)
                #pragma unroll
                for (int j = 0; j < 4; j++)
                    s[i][j] = fmaf(qa[i], ka[j], s[i][j]);
        }
        #pragma unroll
        for (int i = 0; i < 4; i++) {
            float4 r4 = make_float4(s[i][0] * 0.125f, s[i][1] * 0.125f,
                                    s[i][2] * 0.125f, s[i][3] * 0.125f);
            *(float4*)&Ss[(ty * 4 + i) * AT_PAD + tx * 4] = r4;
        }
        __syncthreads();

        // Online softmax: 64 threads, one row each
        if (tid < 64) {
            float* rowp = &Ss[tid * AT_PAD];
            float mold = mrow[tid];
            float tm = mold;
            #pragma unroll 8
            for (int c = 0; c < 64; c++) tm = fmaxf(tm, rowp[c]);
            float al = __expf(mold - tm);
            float sum = 0.f;
            #pragma unroll 8
            for (int c = 0; c < 64; c++) {
                float p = __expf(rowp[c] - tm);
                rowp[c] = p;
                sum += p;
            }
            lrow[tid] = lrow[tid] * al + sum;
            mrow[tid] = tm;
            arow[tid] = al;
        }
        __syncthreads();

        // O = O*alpha + P @ V
        float al[4];
        #pragma unroll
        for (int i = 0; i < 4; i++) al[i] = arow[ty * 4 + i];
        #pragma unroll
        for (int i = 0; i < 4; i++)
            #pragma unroll
            for (int j = 0; j < 4; j++) acc[i][j] *= al[i];
        #pragma unroll
        for (int k = 0; k < 64; k++) {
            float4 v4 = *(float4*)&Vs[k * AT_PAD + tx * 4];
            float va[4] = {v4.x, v4.y, v4.z, v4.w};
            float p[4];
            #pragma unroll
            for (int i = 0; i < 4; i++) p[i] = Ss[(ty * 4 + i) * AT_PAD + k];
            #pragma unroll
            for (int i = 0; i < 4; i++)
                #pragma unroll
                for (int j = 0; j < 4; j++)
                    acc[i][j] = fmaf(p[i], va[j], acc[i][j]);
        }
        __syncthreads();
    }

    int b = bh / HEADS, h = bh % HEADS;
    #pragma unroll
    for (int i = 0; i < 4; i++) {
        int r = ty * 4 + i;
        float inv = 1.f / lrow[r];
        int n = q0 + r;
        float4 o4 = make_float4(acc[i][0] * inv, acc[i][1] * inv,
                                acc[i][2] * inv, acc[i][3] * inv);
        *(float4*)&O[((size_t)(b * SEQ + n)) * D_MODEL + h * DH + tx * 4] = o4;
    }
}

// ---------------------------------------------------------------------------
extern "C" void kernel_launch(void* const* d_in, const int* in_sizes, int n_in,
                              void* d_out, int out_size)
{
    const float* x1    = (const float*)d_in[0];
    const float* x2    = (const float*)d_in[1];
    const float* ln1_g = (const float*)d_in[2];
    const float* ln1_b = (const float*)d_in[3];
    const float* ln2_g = (const float*)d_in[4];
    const float* ln2_b = (const float*)d_in[5];
    const float* wq1 = (const float*)d_in[6];
    const float* bq1 = (const float*)d_in[7];
    const float* wk1 = (const float*)d_in[8];
    const float* bk1 = (const float*)d_in[9];
    const float* wv1 = (const float*)d_in[10];
    const float* bv1 = (const float*)d_in[11];
    const float* wq2 = (const float*)d_in[12];
    const float* bq2 = (const float*)d_in[13];
    const float* wk2 = (const float*)d_in[14];
    const float* bk2 = (const float*)d_in[15];
    const float* wv2 = (const float*)d_in[16];
    const float* bv2 = (const float*)d_in[17];
    const float* wo1 = (const float*)d_in[18];
    const float* bo1 = (const float*)d_in[19];
    const float* wo2 = (const float*)d_in[20];
    const float* bo2 = (const float*)d_in[21];
    float* out = (float*)d_out;

    float* scratch;
    cudaGetSymbolAddress((void**)&scratch, g_scratch);
    float* m1 = scratch;
    float* m2 = m1 + ELEMS;
    float* q1 = m2 + ELEMS;
    float* k1 = q1 + ELEMS;
    float* v1 = k1 + ELEMS;
    float* q2 = v1 + ELEMS;
    float* k2 = q2 + ELEMS;
    float* v2 = k2 + ELEMS;
    float* a1 = v2 + ELEMS;
    float* a2 = a1 + ELEMS;

    ln_kernel<<<ROWS, 256>>>(x1, ln1_g, ln1_b, m1);
    ln_kernel<<<ROWS, 256>>>(x2, ln2_g, ln2_b, m2);

    dim3 gg(D_MODEL / 128, ROWS / 128);   // (6, 64)
    sgemm_kernel<<<gg, 256>>>(m1, wq1, bq1, q1, 1);
    sgemm_kernel<<<gg, 256>>>(m1, wk1, bk1, k1, 1);
    sgemm_kernel<<<gg, 256>>>(m1, wv1, bv1, v1, 1);
    sgemm_kernel<<<gg, 256>>>(m2, wq2, bq2, q2, 1);
    sgemm_kernel<<<gg, 256>>>(m2, wk2, bk2, k2, 1);
    sgemm_kernel<<<gg, 256>>>(m2, wv2, bv2, v2, 1);

    cudaFuncSetAttribute(attn_kernel, cudaFuncAttributeMaxDynamicSharedMemorySize,
                         ATTN_SMEM);
    dim3 ag(SEQ / 64, BATCH * HEADS);     // (16, 96)
    attn_kernel<<<ag, 256, ATTN_SMEM>>>(q1, k2, v2, a1);   // out1 uses q1,k2,v2
    attn_kernel<<<ag, 256, ATTN_SMEM>>>(q2, k1, v1, a2);   // out2 uses q2,k1,v1

    sgemm_kernel<<<gg, 256>>>(a1, wo1, bo1, out, 0);
    sgemm_kernel<<<gg, 256>>>(a2, wo2, bo2, out + ELEMS, 0);
}

// round 4
// speedup vs baseline: 1.2867x; 1.2867x over previous
#include <cuda_runtime.h>
#include <cuda_bf16.h>
#include <stdint.h>
#include <math.h>

#define D_MODEL 768
#define HEADS   12
#define DH      64
#define SEQ     1024
#define BATCH   8
#define ROWS    (BATCH*SEQ)        /* 8192 */
#define ELEMS   (ROWS*D_MODEL)     /* 6291456 */
#define WEL     (D_MODEL*D_MODEL)  /* 589824 */

// fp32 scratch: q1,k1,v1,q2,k2,v2,a1,a2
__device__ float g_f32[8ull * ELEMS];
// bf16 scratch: m1hi,m1lo,m2hi,m2lo,a1hi,a1lo,a2hi,a2lo, then 16 weight halves
__device__ __nv_bfloat16 g_bf16[8ull * ELEMS + 16ull * WEL];

// ---------------------------------------------------------------------------
// PTX helpers
// ---------------------------------------------------------------------------
__device__ __forceinline__ uint32_t smem_u32(const void* p) {
    return (uint32_t)__cvta_generic_to_shared(p);
}
__device__ __forceinline__ void ldsm_x4(uint32_t r[4], uint32_t addr) {
    asm volatile("ldmatrix.sync.aligned.m8n8.x4.shared.b16 {%0,%1,%2,%3}, [%4];"
                 : "=r"(r[0]), "=r"(r[1]), "=r"(r[2]), "=r"(r[3]) : "r"(addr));
}
__device__ __forceinline__ void ldsm_x4_t(uint32_t r[4], uint32_t addr) {
    asm volatile("ldmatrix.sync.aligned.m8n8.x4.trans.shared.b16 {%0,%1,%2,%3}, [%4];"
                 : "=r"(r[0]), "=r"(r[1]), "=r"(r[2]), "=r"(r[3]) : "r"(addr));
}
__device__ __forceinline__ void mma_bf16(float d[4], const uint32_t a[4],
                                         const uint32_t b[2]) {
    asm volatile(
        "mma.sync.aligned.m16n8k16.row.col.f32.bf16.bf16.f32 "
        "{%0,%1,%2,%3}, {%4,%5,%6,%7}, {%8,%9}, {%0,%1,%2,%3};"
        : "+f"(d[0]), "+f"(d[1]), "+f"(d[2]), "+f"(d[3])
        : "r"(a[0]), "r"(a[1]), "r"(a[2]), "r"(a[3]), "r"(b[0]), "r"(b[1]));
}

// ---------------------------------------------------------------------------
// LayerNorm fused with hi/lo bf16 split. One block per row, 256 threads.
// ---------------------------------------------------------------------------
__global__ __launch_bounds__(256)
void ln_split_kernel(const float* __restrict__ x, const float* __restrict__ g,
                     const float* __restrict__ b,
                     __nv_bfloat16* __restrict__ ohi, __nv_bfloat16* __restrict__ olo)
{
    __shared__ float red[16];
    int row = blockIdx.x;
    int tid = threadIdx.x;
    const float* xp = x + (size_t)row * D_MODEL;
    float v0 = xp[tid], v1 = xp[tid + 256], v2 = xp[tid + 512];
    float s  = v0 + v1 + v2;
    float sq = v0*v0 + v1*v1 + v2*v2;
    #pragma unroll
    for (int o = 16; o > 0; o >>= 1) {
        s  += __shfl_down_sync(0xffffffffu, s,  o);
        sq += __shfl_down_sync(0xffffffffu, sq, o);
    }
    int w = tid >> 5, l = tid & 31;
    if (l == 0) { red[w] = s; red[w + 8] = sq; }
    __syncthreads();
    if (tid < 32) {
        float ss = (tid < 8) ? red[tid]     : 0.f;
        float qq = (tid < 8) ? red[tid + 8] : 0.f;
        #pragma unroll
        for (int o = 4; o > 0; o >>= 1) {
            ss += __shfl_down_sync(0xffffffffu, ss, o);
            qq += __shfl_down_sync(0xffffffffu, qq, o);
        }
        if (tid == 0) { red[0] = ss; red[1] = qq; }
    }
    __syncthreads();
    float mu   = red[0] * (1.0f / D_MODEL);
    float var  = red[1] * (1.0f / D_MODEL) - mu * mu;
    float rstd = rsqrtf(var + 1e-5f);
    size_t base = (size_t)row * D_MODEL;
    #pragma unroll
    for (int e = 0; e < 3; e++) {
        int idx = tid + e * 256;
        float v = (e == 0) ? v0 : (e == 1) ? v1 : v2;
        float y = (v - mu) * rstd * g[idx] + b[idx];
        __nv_bfloat16 h = __float2bfloat16(y);
        ohi[base + idx] = h;
        olo[base + idx] = __float2bfloat16(y - __bfloat162float(h));
    }
}

// ---------------------------------------------------------------------------
// Elementwise hi/lo split (float4 vectorized). n must be divisible by 4.
// ---------------------------------------------------------------------------
__global__ __launch_bounds__(256)
void split_kernel(const float* __restrict__ x,
                  __nv_bfloat16* __restrict__ hi, __nv_bfloat16* __restrict__ lo,
                  int n4)
{
    int i = blockIdx.x * blockDim.x + threadIdx.x;
    if (i >= n4) return;
    float4 v = ((const float4*)x)[i];
    float va[4] = {v.x, v.y, v.z, v.w};
    __nv_bfloat16 h[4], l[4];
    #pragma unroll
    for (int e = 0; e < 4; e++) {
        h[e] = __float2bfloat16(va[e]);
        l[e] = __float2bfloat16(va[e] - __bfloat162float(h[e]));
    }
    ((__nv_bfloat162*)hi)[i*2]   = __nv_bfloat162(h[0], h[1]);
    ((__nv_bfloat162*)hi)[i*2+1] = __nv_bfloat162(h[2], h[3]);
    ((__nv_bfloat162*)lo)[i*2]   = __nv_bfloat162(l[0], l[1]);
    ((__nv_bfloat162*)lo)[i*2+1] = __nv_bfloat162(l[2], l[3]);
}

// ---------------------------------------------------------------------------
// Split-bf16 tensor-core GEMM:
//   C[8192,768] = Ahi*Whi + Ahi*Wlo + Alo*Whi + bias   (fp32 accumulate)
// Block tile 128x128, k-chunk 32, 256 threads = 8 warps (2x4), warp tile 64x32.
// mode 0: C row-major; mode 1: head layout [(b*H+h)*SEQ + n]*64 + dh
// ---------------------------------------------------------------------------
__global__ __launch_bounds__(256)
void gemm_bf16(const __nv_bfloat16* __restrict__ Ahi, const __nv_bfloat16* __restrict__ Alo,
               const __nv_bfloat16* __restrict__ Whi, const __nv_bfloat16* __restrict__ Wlo,
               const float* __restrict__ bias, float* __restrict__ C, int mode)
{
    __shared__ __nv_bfloat16 As[128][40];   // 128 x 32 (+8 pad)
    __shared__ __nv_bfloat16 Bs[32][136];   // 32 x 128 (+8 pad)

    int tid  = threadIdx.x;
    int warp = tid >> 5, lane = tid & 31;
    int wm = (warp >> 2) * 64;   // 0,64
    int wn = (warp & 3) * 32;    // 0,32,64,96
    int bm = blockIdx.y * 128, bn = blockIdx.x * 128;

    float acc[4][4][4] = {};     // [mi][nj][frag]

    int ar = tid >> 2;           // 0..63
    int ac = (tid & 3) * 8;      // 0,8,16,24
    int br = tid >> 4;           // 0..15
    int bc = (tid & 15) * 8;     // 0..120

    #pragma unroll 1
    for (int p = 0; p < 3; p++) {
        const __nv_bfloat16* A = (p == 2) ? Alo : Ahi;
        const __nv_bfloat16* W = (p == 1) ? Wlo : Whi;
        #pragma unroll 1
        for (int k0 = 0; k0 < D_MODEL; k0 += 32) {
            #pragma unroll
            for (int rr = 0; rr < 2; rr++) {
                int r = ar + rr * 64;
                *(float4*)&As[r][ac] =
                    *(const float4*)&A[(size_t)(bm + r) * D_MODEL + k0 + ac];
            }
            #pragma unroll
            for (int rr = 0; rr < 2; rr++) {
                int r = br + rr * 16;
                *(float4*)&Bs[r][bc] =
                    *(const float4*)&W[(size_t)(k0 + r) * D_MODEL + bn + bc];
            }
            __syncthreads();
            #pragma unroll
            for (int kk = 0; kk < 32; kk += 16) {
                uint32_t af[4][4];
                uint32_t bf[4][2];
                #pragma unroll
                for (int mi = 0; mi < 4; mi++) {
                    uint32_t addr = smem_u32(
                        &As[wm + mi * 16 + (lane & 15)][kk + (lane >> 4) * 8]);
                    ldsm_x4(af[mi], addr);
                }
                #pragma unroll
                for (int nj2 = 0; nj2 < 2; nj2++) {
                    uint32_t r4[4];
                    uint32_t addr = smem_u32(
                        &Bs[kk + (lane & 15)][wn + nj2 * 16 + (lane >> 4) * 8]);
                    ldsm_x4_t(r4, addr);
                    bf[nj2 * 2 + 0][0] = r4[0]; bf[nj2 * 2 + 0][1] = r4[1];
                    bf[nj2 * 2 + 1][0] = r4[2]; bf[nj2 * 2 + 1][1] = r4[3];
                }
                #pragma unroll
                for (int mi = 0; mi < 4; mi++)
                    #pragma unroll
                    for (int nj = 0; nj < 4; nj++)
                        mma_bf16(acc[mi][nj], af[mi], bf[nj]);
            }
            __syncthreads();
        }
    }

    // Epilogue
    #pragma unroll
    for (int mi = 0; mi < 4; mi++) {
        #pragma unroll
        for (int nj = 0; nj < 4; nj++) {
            int row0 = bm + wm + mi * 16 + (lane >> 2);
            int col  = bn + wn + nj * 8 + (lane & 3) * 2;
            float b0 = bias[col], b1 = bias[col + 1];
            #pragma unroll
            for (int half = 0; half < 2; half++) {
                int row = row0 + half * 8;
                float2 v;
                v.x = acc[mi][nj][half * 2 + 0] + b0;
                v.y = acc[mi][nj][half * 2 + 1] + b1;
                if (mode == 0) {
                    *(float2*)&C[(size_t)row * D_MODEL + col] = v;
                } else {
                    int bb = row >> 10;
                    int n  = row & (SEQ - 1);
                    int h  = col >> 6;
                    int dh = col & 63;
                    *(float2*)&C[(((size_t)(bb * HEADS + h)) * SEQ + n) * DH + dh] = v;
                }
            }
        }
    }
}

// ---------------------------------------------------------------------------
// Flash attention (fp32, unchanged working kernel from R1).
// ---------------------------------------------------------------------------
#define AT_PAD 68
#define ATTN_SMEM ((4 * 64 * AT_PAD + 3 * 64) * (int)sizeof(float))

__global__ __launch_bounds__(256)
void attn_kernel(const float* __restrict__ Q, const float* __restrict__ K,
                 const float* __restrict__ V, float* __restrict__ O)
{
    extern __shared__ float sm[];
    float* Qt   = sm;
    float* Kt   = Qt + 64 * AT_PAD;
    float* Vs   = Kt + 64 * AT_PAD;
    float* Ss   = Vs + 64 * AT_PAD;
    float* mrow = Ss + 64 * AT_PAD;
    float* lrow = mrow + 64;
    float* arow = lrow + 64;

    int tid = threadIdx.x;
    int bh  = blockIdx.y;
    int q0  = blockIdx.x * 64;
    const float* Qp = Q + (size_t)bh * SEQ * DH;
    const float* Kp = K + (size_t)bh * SEQ * DH;
    const float* Vp = V + (size_t)bh * SEQ * DH;

    int lr = tid >> 4;
    int lc = (tid & 15) << 2;
    #pragma unroll
    for (int r = lr; r < 64; r += 16) {
        float4 q4 = *(const float4*)&Qp[(size_t)(q0 + r) * DH + lc];
        Qt[(lc + 0) * AT_PAD + r] = q4.x;
        Qt[(lc + 1) * AT_PAD + r] = q4.y;
        Qt[(lc + 2) * AT_PAD + r] = q4.z;
        Qt[(lc + 3) * AT_PAD + r] = q4.w;
    }
    if (tid < 64) { mrow[tid] = -INFINITY; lrow[tid] = 0.f; }

    int ty = tid >> 4, tx = tid & 15;
    float acc[4][4] = {};
    __syncthreads();

    for (int kv0 = 0; kv0 < SEQ; kv0 += 64) {
        #pragma unroll
        for (int r = lr; r < 64; r += 16) {
            float4 k4 = *(const float4*)&Kp[(size_t)(kv0 + r) * DH + lc];
            Kt[(lc + 0) * AT_PAD + r] = k4.x;
            Kt[(lc + 1) * AT_PAD + r] = k4.y;
            Kt[(lc + 2) * AT_PAD + r] = k4.z;
            Kt[(lc + 3) * AT_PAD + r] = k4.w;
            float4 v4 = *(const float4*)&Vp[(size_t)(kv0 + r) * DH + lc];
            *(float4*)&Vs[r * AT_PAD + lc] = v4;
        }
        __syncthreads();

        float s[4][4] = {};
        #pragma unroll
        for (int d = 0; d < 64; d++) {
            float4 q4 = *(float4*)&Qt[d * AT_PAD + ty * 4];
            float4 k4 = *(float4*)&Kt[d * AT_PAD + tx * 4];
            float qa[4] = {q4.x, q4.y, q4.z, q4.w};
            float ka[4] = {k4.x, k4.y, k4.z, k4.w};
            #pragma unroll
            for (int i = 0; i < 4; i++)
                #pragma unroll
                for (int j = 0; j < 4; j++)
                    s[i][j] = fmaf(qa[i], ka[j], s[i][j]);
        }
        #pragma unroll
        for (int i = 0; i < 4; i++) {
            float4 r4 = make_float4(s[i][0] * 0.125f, s[i][1] * 0.125f,
                                    s[i][2] * 0.125f, s[i][3] * 0.125f);
            *(float4*)&Ss[(ty * 4 + i) * AT_PAD + tx * 4] = r4;
        }
        __syncthreads();

        if (tid < 64) {
            float* rowp = &Ss[tid * AT_PAD];
            float mold = mrow[tid];
            float tm = mold;
            #pragma unroll 8
            for (int c = 0; c < 64; c++) tm = fmaxf(tm, rowp[c]);
            float al = __expf(mold - tm);
            float sum = 0.f;
            #pragma unroll 8
            for (int c = 0; c < 64; c++) {
                float p = __expf(rowp[c] - tm);
                rowp[c] = p;
                sum += p;
            }
            lrow[tid] = lrow[tid] * al + sum;
            mrow[tid] = tm;
            arow[tid] = al;
        }
        __syncthreads();

        float al[4];
        #pragma unroll
        for (int i = 0; i < 4; i++) al[i] = arow[ty * 4 + i];
        #pragma unroll
        for (int i = 0; i < 4; i++)
            #pragma unroll
            for (int j = 0; j < 4; j++) acc[i][j] *= al[i];
        #pragma unroll
        for (int k = 0; k < 64; k++) {
            float4 v4 = *(float4*)&Vs[k * AT_PAD + tx * 4];
            float va[4] = {v4.x, v4.y, v4.z, v4.w};
            float p[4];
            #pragma unroll
            for (int i = 0; i < 4; i++) p[i] = Ss[(ty * 4 + i) * AT_PAD + k];
            #pragma unroll
            for (int i = 0; i < 4; i++)
                #pragma unroll
                for (int j = 0; j < 4; j++)
                    acc[i][j] = fmaf(p[i], va[j], acc[i][j]);
        }
        __syncthreads();
    }

    int b = bh / HEADS, h = bh % HEADS;
    #pragma unroll
    for (int i = 0; i < 4; i++) {
        int r = ty * 4 + i;
        float inv = 1.f / lrow[r];
        int n = q0 + r;
        float4 o4 = make_float4(acc[i][0] * inv, acc[i][1] * inv,
                                acc[i][2] * inv, acc[i][3] * inv);
        *(float4*)&O[((size_t)(b * SEQ + n)) * D_MODEL + h * DH + tx * 4] = o4;
    }
}

// ---------------------------------------------------------------------------
extern "C" void kernel_launch(void* const* d_in, const int* in_sizes, int n_in,
                              void* d_out, int out_size)
{
    const float* x1    = (const float*)d_in[0];
    const float* x2    = (const float*)d_in[1];
    const float* ln1_g = (const float*)d_in[2];
    const float* ln1_b = (const float*)d_in[3];
    const float* ln2_g = (const float*)d_in[4];
    const float* ln2_b = (const float*)d_in[5];
    const float* w_in[8] = {
        (const float*)d_in[6],  (const float*)d_in[8],  (const float*)d_in[10],
        (const float*)d_in[12], (const float*)d_in[14], (const float*)d_in[16],
        (const float*)d_in[18], (const float*)d_in[20]
    }; // wq1,wk1,wv1,wq2,wk2,wv2,wo1,wo2
    const float* b_in[8] = {
        (const float*)d_in[7],  (const float*)d_in[9],  (const float*)d_in[11],
        (const float*)d_in[13], (const float*)d_in[15], (const float*)d_in[17],
        (const float*)d_in[19], (const float*)d_in[21]
    };
    float* out = (float*)d_out;

    float* f32;
    __nv_bfloat16* bf;
    cudaGetSymbolAddress((void**)&f32, g_f32);
    cudaGetSymbolAddress((void**)&bf, g_bf16);

    float* q1 = f32;
    float* k1 = q1 + ELEMS;
    float* v1 = k1 + ELEMS;
    float* q2 = v1 + ELEMS;
    float* k2 = q2 + ELEMS;
    float* v2 = k2 + ELEMS;
    float* a1 = v2 + ELEMS;
    float* a2 = a1 + ELEMS;

    __nv_bfloat16* m1hi = bf;
    __nv_bfloat16* m1lo = m1hi + ELEMS;
    __nv_bfloat16* m2hi = m1lo + ELEMS;
    __nv_bfloat16* m2lo = m2hi + ELEMS;
    __nv_bfloat16* a1hi = m2lo + ELEMS;
    __nv_bfloat16* a1lo = a1hi + ELEMS;
    __nv_bfloat16* a2hi = a1lo + ELEMS;
    __nv_bfloat16* a2lo = a2hi + ELEMS;
    __nv_bfloat16* wbase = a2lo + ELEMS;

    // Split the 8 weight matrices into bf16 hi/lo
    for (int i = 0; i < 8; i++) {
        split_kernel<<<(WEL/4 + 255)/256, 256>>>(w_in[i], wbase + (size_t)i*2*WEL,
                                                 wbase + (size_t)i*2*WEL + WEL, WEL/4);
    }

    // LayerNorm + split
    ln_split_kernel<<<ROWS, 256>>>(x1, ln1_g, ln1_b, m1hi, m1lo);
    ln_split_kernel<<<ROWS, 256>>>(x2, ln2_g, ln2_b, m2hi, m2lo);

    dim3 gg(D_MODEL / 128, ROWS / 128);   // (6, 64)
    // QKV projections (mode 1 -> head layout)
    float* qkv[6] = {q1, k1, v1, q2, k2, v2};
    for (int i = 0; i < 6; i++) {
        __nv_bfloat16* ahi = (i < 3) ? m1hi : m2hi;
        __nv_bfloat16* alo = (i < 3) ? m1lo : m2lo;
        gemm_bf16<<<gg, 256>>>(ahi, alo,
                               wbase + (size_t)i*2*WEL, wbase + (size_t)i*2*WEL + WEL,
                               b_in[i], qkv[i], 1);
    }

    cudaFuncSetAttribute(attn_kernel, cudaFuncAttributeMaxDynamicSharedMemorySize,
                         ATTN_SMEM);
    dim3 ag(SEQ / 64, BATCH * HEADS);     // (16, 96)
    attn_kernel<<<ag, 256, ATTN_SMEM>>>(q1, k2, v2, a1);
    attn_kernel<<<ag, 256, ATTN_SMEM>>>(q2, k1, v1, a2);

    // Split attention outputs, then output projections (mode 0)
    split_kernel<<<(ELEMS/4 + 255)/256, 256>>>(a1, a1hi, a1lo, ELEMS/4);
    split_kernel<<<(ELEMS/4 + 255)/256, 256>>>(a2, a2hi, a2lo, ELEMS/4);

    gemm_bf16<<<gg, 256>>>(a1hi, a1lo, wbase + 6ull*2*WEL, wbase + 6ull*2*WEL + WEL,
                           b_in[6], out, 0);
    gemm_bf16<<<gg, 256>>>(a2hi, a2lo, wbase + 7ull*2*WEL, wbase + 7ull*2*WEL + WEL,
                           b_in[7], out + ELEMS, 0);
}

// round 5
// speedup vs baseline: 1.2989x; 1.0095x over previous
#include <cuda_runtime.h>
#include <cuda_bf16.h>
#include <stdint.h>
#include <math.h>

#define D_MODEL 768
#define HEADS   12
#define DH      64
#define SEQ     1024
#define BATCH   8
#define ROWS    (BATCH*SEQ)        /* 8192 */
#define ELEMS   (ROWS*D_MODEL)     /* 6291456 */
#define WEL     (D_MODEL*D_MODEL)  /* 589824 */

// fp32 scratch: q1,k1,v1,q2,k2,v2,a1,a2
__device__ float g_f32[8ull * ELEMS];
// bf16 scratch: m1hi,m1lo,m2hi,m2lo,a1hi,a1lo,a2hi,a2lo, then 16 weight halves
__device__ __nv_bfloat16 g_bf16[8ull * ELEMS + 16ull * WEL];

// ---------------------------------------------------------------------------
// PTX helpers
// ---------------------------------------------------------------------------
__device__ __forceinline__ uint32_t smem_u32(const void* p) {
    return (uint32_t)__cvta_generic_to_shared(p);
}
__device__ __forceinline__ void ldsm_x4(uint32_t r[4], uint32_t addr) {
    asm volatile("ldmatrix.sync.aligned.m8n8.x4.shared.b16 {%0,%1,%2,%3}, [%4];"
                 : "=r"(r[0]), "=r"(r[1]), "=r"(r[2]), "=r"(r[3]) : "r"(addr));
}
__device__ __forceinline__ void ldsm_x4_t(uint32_t r[4], uint32_t addr) {
    asm volatile("ldmatrix.sync.aligned.m8n8.x4.trans.shared.b16 {%0,%1,%2,%3}, [%4];"
                 : "=r"(r[0]), "=r"(r[1]), "=r"(r[2]), "=r"(r[3]) : "r"(addr));
}
__device__ __forceinline__ void mma_bf16(float d[4], const uint32_t a[4],
                                         const uint32_t b[2]) {
    asm volatile(
        "mma.sync.aligned.m16n8k16.row.col.f32.bf16.bf16.f32 "
        "{%0,%1,%2,%3}, {%4,%5,%6,%7}, {%8,%9}, {%0,%1,%2,%3};"
        : "+f"(d[0]), "+f"(d[1]), "+f"(d[2]), "+f"(d[3])
        : "r"(a[0]), "r"(a[1]), "r"(a[2]), "r"(a[3]), "r"(b[0]), "r"(b[1]));
}

// ---------------------------------------------------------------------------
// LayerNorm fused with hi/lo bf16 split. One block per row, 256 threads.
// ---------------------------------------------------------------------------
__global__ __launch_bounds__(256)
void ln_split_kernel(const float* __restrict__ x, const float* __restrict__ g,
                     const float* __restrict__ b,
                     __nv_bfloat16* __restrict__ ohi, __nv_bfloat16* __restrict__ olo)
{
    __shared__ float red[16];
    int row = blockIdx.x;
    int tid = threadIdx.x;
    const float* xp = x + (size_t)row * D_MODEL;
    float v0 = xp[tid], v1 = xp[tid + 256], v2 = xp[tid + 512];
    float s  = v0 + v1 + v2;
    float sq = v0*v0 + v1*v1 + v2*v2;
    #pragma unroll
    for (int o = 16; o > 0; o >>= 1) {
        s  += __shfl_down_sync(0xffffffffu, s,  o);
        sq += __shfl_down_sync(0xffffffffu, sq, o);
    }
    int w = tid >> 5, l = tid & 31;
    if (l == 0) { red[w] = s; red[w + 8] = sq; }
    __syncthreads();
    if (tid < 32) {
        float ss = (tid < 8) ? red[tid]     : 0.f;
        float qq = (tid < 8) ? red[tid + 8] : 0.f;
        #pragma unroll
        for (int o = 4; o > 0; o >>= 1) {
            ss += __shfl_down_sync(0xffffffffu, ss, o);
            qq += __shfl_down_sync(0xffffffffu, qq, o);
        }
        if (tid == 0) { red[0] = ss; red[1] = qq; }
    }
    __syncthreads();
    float mu   = red[0] * (1.0f / D_MODEL);
    float var  = red[1] * (1.0f / D_MODEL) - mu * mu;
    float rstd = rsqrtf(var + 1e-5f);
    size_t base = (size_t)row * D_MODEL;
    #pragma unroll
    for (int e = 0; e < 3; e++) {
        int idx = tid + e * 256;
        float v = (e == 0) ? v0 : (e == 1) ? v1 : v2;
        float y = (v - mu) * rstd * g[idx] + b[idx];
        __nv_bfloat16 h = __float2bfloat16(y);
        ohi[base + idx] = h;
        olo[base + idx] = __float2bfloat16(y - __bfloat162float(h));
    }
}

// ---------------------------------------------------------------------------
// Elementwise hi/lo split (float4 vectorized). n must be divisible by 4.
// ---------------------------------------------------------------------------
__global__ __launch_bounds__(256)
void split_kernel(const float* __restrict__ x,
                  __nv_bfloat16* __restrict__ hi, __nv_bfloat16* __restrict__ lo,
                  int n4)
{
    int i = blockIdx.x * blockDim.x + threadIdx.x;
    if (i >= n4) return;
    float4 v = ((const float4*)x)[i];
    float va[4] = {v.x, v.y, v.z, v.w};
    __nv_bfloat16 h[4], l[4];
    #pragma unroll
    for (int e = 0; e < 4; e++) {
        h[e] = __float2bfloat16(va[e]);
        l[e] = __float2bfloat16(va[e] - __bfloat162float(h[e]));
    }
    ((__nv_bfloat162*)hi)[i*2]   = __nv_bfloat162(h[0], h[1]);
    ((__nv_bfloat162*)hi)[i*2+1] = __nv_bfloat162(h[2], h[3]);
    ((__nv_bfloat162*)lo)[i*2]   = __nv_bfloat162(l[0], l[1]);
    ((__nv_bfloat162*)lo)[i*2+1] = __nv_bfloat162(l[2], l[3]);
}

// ---------------------------------------------------------------------------
// Split-bf16 tensor-core GEMM:
//   C[8192,768] = Ahi*Whi + Ahi*Wlo + Alo*Whi + bias   (fp32 accumulate)
// Block tile 128x128, k-chunk 32, 256 threads = 8 warps (2x4), warp tile 64x32.
// mode 0: C row-major; mode 1: head layout [(b*H+h)*SEQ + n]*64 + dh
// ---------------------------------------------------------------------------
__global__ __launch_bounds__(256)
void gemm_bf16(const __nv_bfloat16* __restrict__ Ahi, const __nv_bfloat16* __restrict__ Alo,
               const __nv_bfloat16* __restrict__ Whi, const __nv_bfloat16* __restrict__ Wlo,
               const float* __restrict__ bias, float* __restrict__ C, int mode)
{
    __shared__ __nv_bfloat16 As[128][40];   // 128 x 32 (+8 pad)
    __shared__ __nv_bfloat16 Bs[32][136];   // 32 x 128 (+8 pad)

    int tid  = threadIdx.x;
    int warp = tid >> 5, lane = tid & 31;
    int wm = (warp >> 2) * 64;   // 0,64
    int wn = (warp & 3) * 32;    // 0,32,64,96
    int bm = blockIdx.y * 128, bn = blockIdx.x * 128;

    float acc[4][4][4] = {};     // [mi][nj][frag]

    int ar = tid >> 2;           // 0..63
    int ac = (tid & 3) * 8;      // 0,8,16,24
    int br = tid >> 4;           // 0..15
    int bc = (tid & 15) * 8;     // 0..120

    #pragma unroll 1
    for (int p = 0; p < 3; p++) {
        const __nv_bfloat16* A = (p == 2) ? Alo : Ahi;
        const __nv_bfloat16* W = (p == 1) ? Wlo : Whi;
        #pragma unroll 1
        for (int k0 = 0; k0 < D_MODEL; k0 += 32) {
            #pragma unroll
            for (int rr = 0; rr < 2; rr++) {
                int r = ar + rr * 64;
                *(float4*)&As[r][ac] =
                    *(const float4*)&A[(size_t)(bm + r) * D_MODEL + k0 + ac];
            }
            #pragma unroll
            for (int rr = 0; rr < 2; rr++) {
                int r = br + rr * 16;
                *(float4*)&Bs[r][bc] =
                    *(const float4*)&W[(size_t)(k0 + r) * D_MODEL + bn + bc];
            }
            __syncthreads();
            #pragma unroll
            for (int kk = 0; kk < 32; kk += 16) {
                uint32_t af[4][4];
                uint32_t bf[4][2];
                #pragma unroll
                for (int mi = 0; mi < 4; mi++) {
                    uint32_t addr = smem_u32(
                        &As[wm + mi * 16 + (lane & 15)][kk + (lane >> 4) * 8]);
                    ldsm_x4(af[mi], addr);
                }
                #pragma unroll
                for (int nj2 = 0; nj2 < 2; nj2++) {
                    uint32_t r4[4];
                    uint32_t addr = smem_u32(
                        &Bs[kk + (lane & 15)][wn + nj2 * 16 + (lane >> 4) * 8]);
                    ldsm_x4_t(r4, addr);
                    bf[nj2 * 2 + 0][0] = r4[0]; bf[nj2 * 2 + 0][1] = r4[1];
                    bf[nj2 * 2 + 1][0] = r4[2]; bf[nj2 * 2 + 1][1] = r4[3];
                }
                #pragma unroll
                for (int mi = 0; mi < 4; mi++)
                    #pragma unroll
                    for (int nj = 0; nj < 4; nj++)
                        mma_bf16(acc[mi][nj], af[mi], bf[nj]);
            }
            __syncthreads();
        }
    }

    // Epilogue
    #pragma unroll
    for (int mi = 0; mi < 4; mi++) {
        #pragma unroll
        for (int nj = 0; nj < 4; nj++) {
            int row0 = bm + wm + mi * 16 + (lane >> 2);
            int col  = bn + wn + nj * 8 + (lane & 3) * 2;
            float b0 = bias[col], b1 = bias[col + 1];
            #pragma unroll
            for (int half = 0; half < 2; half++) {
                int row = row0 + half * 8;
                float2 v;
                v.x = acc[mi][nj][half * 2 + 0] + b0;
                v.y = acc[mi][nj][half * 2 + 1] + b1;
                if (mode == 0) {
                    *(float2*)&C[(size_t)row * D_MODEL + col] = v;
                } else {
                    int bb = row >> 10;
                    int n  = row & (SEQ - 1);
                    int h  = col >> 6;
                    int dh = col & 63;
                    *(float2*)&C[(((size_t)(bb * HEADS + h)) * SEQ + n) * DH + dh] = v;
                }
            }
        }
    }
}

// ---------------------------------------------------------------------------
// Flash attention (fp32, unchanged working kernel from R1).
// ---------------------------------------------------------------------------
#define AT_PAD 68
#define ATTN_SMEM ((4 * 64 * AT_PAD + 3 * 64) * (int)sizeof(float))

__global__ __launch_bounds__(256)
void attn_kernel(const float* __restrict__ Q, const float* __restrict__ K,
                 const float* __restrict__ V, float* __restrict__ O)
{
    extern __shared__ float sm[];
    float* Qt   = sm;
    float* Kt   = Qt + 64 * AT_PAD;
    float* Vs   = Kt + 64 * AT_PAD;
    float* Ss   = Vs + 64 * AT_PAD;
    float* mrow = Ss + 64 * AT_PAD;
    float* lrow = mrow + 64;
    float* arow = lrow + 64;

    int tid = threadIdx.x;
    int bh  = blockIdx.y;
    int q0  = blockIdx.x * 64;
    const float* Qp = Q + (size_t)bh * SEQ * DH;
    const float* Kp = K + (size_t)bh * SEQ * DH;
    const float* Vp = V + (size_t)bh * SEQ * DH;

    int lr = tid >> 4;
    int lc = (tid & 15) << 2;
    #pragma unroll
    for (int r = lr; r < 64; r += 16) {
        float4 q4 = *(const float4*)&Qp[(size_t)(q0 + r) * DH + lc];
        Qt[(lc + 0) * AT_PAD + r] = q4.x;
        Qt[(lc + 1) * AT_PAD + r] = q4.y;
        Qt[(lc + 2) * AT_PAD + r] = q4.z;
        Qt[(lc + 3) * AT_PAD + r] = q4.w;
    }
    if (tid < 64) { mrow[tid] = -INFINITY; lrow[tid] = 0.f; }

    int ty = tid >> 4, tx = tid & 15;
    float acc[4][4] = {};
    __syncthreads();

    for (int kv0 = 0; kv0 < SEQ; kv0 += 64) {
        #pragma unroll
        for (int r = lr; r < 64; r += 16) {
            float4 k4 = *(const float4*)&Kp[(size_t)(kv0 + r) * DH + lc];
            Kt[(lc + 0) * AT_PAD + r] = k4.x;
            Kt[(lc + 1) * AT_PAD + r] = k4.y;
            Kt[(lc + 2) * AT_PAD + r] = k4.z;
            Kt[(lc + 3) * AT_PAD + r] = k4.w;
            float4 v4 = *(const float4*)&Vp[(size_t)(kv0 + r) * DH + lc];
            *(float4*)&Vs[r * AT_PAD + lc] = v4;
        }
        __syncthreads();

        float s[4][4] = {};
        #pragma unroll
        for (int d = 0; d < 64; d++) {
            float4 q4 = *(float4*)&Qt[d * AT_PAD + ty * 4];
            float4 k4 = *(float4*)&Kt[d * AT_PAD + tx * 4];
            float qa[4] = {q4.x, q4.y, q4.z, q4.w};
            float ka[4] = {k4.x, k4.y, k4.z, k4.w};
            #pragma unroll
            for (int i = 0; i < 4; i++)
                #pragma unroll
                for (int j = 0; j < 4; j++)
                    s[i][j] = fmaf(qa[i], ka[j], s[i][j]);
        }
        #pragma unroll
        for (int i = 0; i < 4; i++) {
            float4 r4 = make_float4(s[i][0] * 0.125f, s[i][1] * 0.125f,
                                    s[i][2] * 0.125f, s[i][3] * 0.125f);
            *(float4*)&Ss[(ty * 4 + i) * AT_PAD + tx * 4] = r4;
        }
        __syncthreads();

        if (tid < 64) {
            float* rowp = &Ss[tid * AT_PAD];
            float mold = mrow[tid];
            float tm = mold;
            #pragma unroll 8
            for (int c = 0; c < 64; c++) tm = fmaxf(tm, rowp[c]);
            float al = __expf(mold - tm);
            float sum = 0.f;
            #pragma unroll 8
            for (int c = 0; c < 64; c++) {
                float p = __expf(rowp[c] - tm);
                rowp[c] = p;
                sum += p;
            }
            lrow[tid] = lrow[tid] * al + sum;
            mrow[tid] = tm;
            arow[tid] = al;
        }
        __syncthreads();

        float al[4];
        #pragma unroll
        for (int i = 0; i < 4; i++) al[i] = arow[ty * 4 + i];
        #pragma unroll
        for (int i = 0; i < 4; i++)
            #pragma unroll
            for (int j = 0; j < 4; j++) acc[i][j] *= al[i];
        #pragma unroll
        for (int k = 0; k < 64; k++) {
            float4 v4 = *(float4*)&Vs[k * AT_PAD + tx * 4];
            float va[4] = {v4.x, v4.y, v4.z, v4.w};
            float p[4];
            #pragma unroll
            for (int i = 0; i < 4; i++) p[i] = Ss[(ty * 4 + i) * AT_PAD + k];
            #pragma unroll
            for (int i = 0; i < 4; i++)
                #pragma unroll
                for (int j = 0; j < 4; j++)
                    acc[i][j] = fmaf(p[i], va[j], acc[i][j]);
        }
        __syncthreads();
    }

    int b = bh / HEADS, h = bh % HEADS;
    #pragma unroll
    for (int i = 0; i < 4; i++) {
        int r = ty * 4 + i;
        float inv = 1.f / lrow[r];
        int n = q0 + r;
        float4 o4 = make_float4(acc[i][0] * inv, acc[i][1] * inv,
                                acc[i][2] * inv, acc[i][3] * inv);
        *(float4*)&O[((size_t)(b * SEQ + n)) * D_MODEL + h * DH + tx * 4] = o4;
    }
}

// ---------------------------------------------------------------------------
extern "C" void kernel_launch(void* const* d_in, const int* in_sizes, int n_in,
                              void* d_out, int out_size)
{
    const float* x1    = (const float*)d_in[0];
    const float* x2    = (const float*)d_in[1];
    const float* ln1_g = (const float*)d_in[2];
    const float* ln1_b = (const float*)d_in[3];
    const float* ln2_g = (const float*)d_in[4];
    const float* ln2_b = (const float*)d_in[5];
    const float* w_in[8] = {
        (const float*)d_in[6],  (const float*)d_in[8],  (const float*)d_in[10],
        (const float*)d_in[12], (const float*)d_in[14], (const float*)d_in[16],
        (const float*)d_in[18], (const float*)d_in[20]
    }; // wq1,wk1,wv1,wq2,wk2,wv2,wo1,wo2
    const float* b_in[8] = {
        (const float*)d_in[7],  (const float*)d_in[9],  (const float*)d_in[11],
        (const float*)d_in[13], (const float*)d_in[15], (const float*)d_in[17],
        (const float*)d_in[19], (const float*)d_in[21]
    };
    float* out = (float*)d_out;

    float* f32;
    __nv_bfloat16* bf;
    cudaGetSymbolAddress((void**)&f32, g_f32);
    cudaGetSymbolAddress((void**)&bf, g_bf16);

    float* q1 = f32;
    float* k1 = q1 + ELEMS;
    float* v1 = k1 + ELEMS;
    float* q2 = v1 + ELEMS;
    float* k2 = q2 + ELEMS;
    float* v2 = k2 + ELEMS;
    float* a1 = v2 + ELEMS;
    float* a2 = a1 + ELEMS;

    __nv_bfloat16* m1hi = bf;
    __nv_bfloat16* m1lo = m1hi + ELEMS;
    __nv_bfloat16* m2hi = m1lo + ELEMS;
    __nv_bfloat16* m2lo = m2hi + ELEMS;
    __nv_bfloat16* a1hi = m2lo + ELEMS;
    __nv_bfloat16* a1lo = a1hi + ELEMS;
    __nv_bfloat16* a2hi = a1lo + ELEMS;
    __nv_bfloat16* a2lo = a2hi + ELEMS;
    __nv_bfloat16* wbase = a2lo + ELEMS;

    // Split the 8 weight matrices into bf16 hi/lo
    for (int i = 0; i < 8; i++) {
        split_kernel<<<(WEL/4 + 255)/256, 256>>>(w_in[i], wbase + (size_t)i*2*WEL,
                                                 wbase + (size_t)i*2*WEL + WEL, WEL/4);
    }

    // LayerNorm + split
    ln_split_kernel<<<ROWS, 256>>>(x1, ln1_g, ln1_b, m1hi, m1lo);
    ln_split_kernel<<<ROWS, 256>>>(x2, ln2_g, ln2_b, m2hi, m2lo);

    dim3 gg(D_MODEL / 128, ROWS / 128);   // (6, 64)
    // QKV projections (mode 1 -> head layout)
    float* qkv[6] = {q1, k1, v1, q2, k2, v2};
    for (int i = 0; i < 6; i++) {
        __nv_bfloat16* ahi = (i < 3) ? m1hi : m2hi;
        __nv_bfloat16* alo = (i < 3) ? m1lo : m2lo;
        gemm_bf16<<<gg, 256>>>(ahi, alo,
                               wbase + (size_t)i*2*WEL, wbase + (size_t)i*2*WEL + WEL,
                               b_in[i], qkv[i], 1);
    }

    cudaFuncSetAttribute(attn_kernel, cudaFuncAttributeMaxDynamicSharedMemorySize,
                         ATTN_SMEM);
    dim3 ag(SEQ / 64, BATCH * HEADS);     // (16, 96)
    attn_kernel<<<ag, 256, ATTN_SMEM>>>(q1, k2, v2, a1);
    attn_kernel<<<ag, 256, ATTN_SMEM>>>(q2, k1, v1, a2);

    // Split attention outputs, then output projections (mode 0)
    split_kernel<<<(ELEMS/4 + 255)/256, 256>>>(a1, a1hi, a1lo, ELEMS/4);
    split_kernel<<<(ELEMS/4 + 255)/256, 256>>>(a2, a2hi, a2lo, ELEMS/4);

    gemm_bf16<<<gg, 256>>>(a1hi, a1lo, wbase + 6ull*2*WEL, wbase + 6ull*2*WEL + WEL,
                           b_in[6], out, 0);
    gemm_bf16<<<gg, 256>>>(a2hi, a2lo, wbase + 7ull*2*WEL, wbase + 7ull*2*WEL + WEL,
                           b_in[7], out + ELEMS, 0);
}